// round 12
// baseline (speedup 1.0000x reference)
#include <cuda_runtime.h>
#include <cuda_fp16.h>
#include <cstdint>

// Problem constants
#define B_DIM   512
#define HALF_B  256
#define IN_DIM  65536
#define OUT_DIM 16384
#define K_DIM   32
#define OTILE   8

#define TILES_PER_STRIP 8
#define TSTRIP_H 512            // transpose strip-blocks per half (4096/8)
#define GBLK_H   2048           // gather blocks per half
#define GRID_WORK (2 * TSTRIP_H + 2 * GBLK_H)  // 5120
#define GRID_TOTAL (GRID_WORK + 1)             // +1 cleanup block

// 64 MB scratch for transposed x in fp16: xt[in][b]
__device__ __half g_xt_h[(size_t)IN_DIM * B_DIM];

// Gating state. Zero-initialized at load; cleanup block re-zeroes at the end
// of every execution so each graph replay starts clean.
__device__ int g_tdone[2];      // strip-blocks completed per half (target 512)
__device__ int g_gpassed;

// Bit-reinterpretation helpers
__device__ __forceinline__ unsigned int h2_to_u32(__half2 h) {
    union { __half2 h; unsigned int u; } c; c.h = h; return c.u;
}
__device__ __forceinline__ float2 u32_to_f2(unsigned int u) {
    union { unsigned int u; __half2 h; } c; c.u = u;
    return __half22float2(c.h);
}

// Shared-memory shapes (union -> fused footprint = max, not sum)
struct SmemT {
    float4 tile4[32][33];                      // 16.9 KB
};
struct SmemG {
    int4   sidx4[OTILE][K_DIM / 4];
    float4 sw4[OTILE][K_DIM / 4];
    float  sbias[OTILE];
    float  sout[OTILE][HALF_B + 8];
};
union SmemU { SmemT t; SmemG g; };

// ---------------------------------------------------------------------------
// Transpose strip: 8 consecutive 32b x 128in tiles (one b-band, 1024 in-cols).
// Register double-buffer: loads for tile n+1 are issued before tile n's
// smem/convert/store phase, keeping LDGs in flight across the barriers.
// ---------------------------------------------------------------------------
__device__ __forceinline__ void transpose_strip(
    const float* __restrict__ x, int j, int half, SmemT& s)
{
    const int band    = j >> 6;                // 0..7 within half
    const int in_base = (j & 63) << 10;        // 0..64512 step 1024
    const int b0      = half * HALF_B + band * 32;

    const int t  = threadIdx.x;
    const int c4 = t & 31;                     // float4 col within tile
    const int r0 = t >> 5;                     // 0..7

    // Per-row base pointers (row r handled at r0, r0+8, r0+16, r0+24)
    const float* row[4];
    #pragma unroll
    for (int it = 0; it < 4; it++)
        row[it] = x + (size_t)(b0 + r0 + 8 * it) * IN_DIM + in_base + 4 * c4;

    // Conversion-phase indices
    const int i  = t >> 1;                     // in-row within tile 0..127
    const int p  = t & 1;                      // b-chunk (16 b = 32B)
    const int c  = i >> 2;
    const int cc = i & 3;

    float4 cur[4], nxt[4];
    #pragma unroll
    for (int it = 0; it < 4; it++) cur[it] = *(const float4*)(row[it]);

    #pragma unroll
    for (int tile = 0; tile < TILES_PER_STRIP; tile++) {
        // Prefetch next tile (independent of everything below -> stays in
        // flight across both barriers of this iteration).
        if (tile < TILES_PER_STRIP - 1) {
            #pragma unroll
            for (int it = 0; it < 4; it++)
                nxt[it] = *(const float4*)(row[it] + (tile + 1) * 128);
        }

        // Stage current tile to smem
        #pragma unroll
        for (int it = 0; it < 4; it++)
            s.tile4[r0 + 8 * it][c4] = cur[it];
        __syncthreads();

        // Convert + store: thread owns in-row i, 16-b chunk p (32B store)
        __half2 h2[8];
        #pragma unroll
        for (int jj = 0; jj < 8; jj++) {
            const float f0 = ((const float*)&s.tile4[16 * p + 2 * jj + 0][c])[cc];
            const float f1 = ((const float*)&s.tile4[16 * p + 2 * jj + 1][c])[cc];
            h2[jj] = __floats2half2_rn(f0, f1);
        }
        uint4 u0, u1;
        u0.x = h2_to_u32(h2[0]); u0.y = h2_to_u32(h2[1]);
        u0.z = h2_to_u32(h2[2]); u0.w = h2_to_u32(h2[3]);
        u1.x = h2_to_u32(h2[4]); u1.y = h2_to_u32(h2[5]);
        u1.z = h2_to_u32(h2[6]); u1.w = h2_to_u32(h2[7]);

        const int in0 = in_base + tile * 128;
        uint4* dst = (uint4*)&g_xt_h[(size_t)(in0 + i) * B_DIM + b0 + 16 * p];
        dst[0] = u0;
        dst[1] = u1;

        __syncthreads();                       // protect smem for next tile

        #pragma unroll
        for (int it = 0; it < 4; it++) cur[it] = nxt[it];
    }

    if (t == 0) {
        __threadfence();                       // release all strip stores
        atomicAdd(&g_tdone[half], 1);
    }
}

// ---------------------------------------------------------------------------
// Gather block body: 8 outputs x one b-half. Warp per output; lane owns
// 8 b-rows via one LDG.128 per (o,k) -> 512B contiguous column reads.
// Gates on g_tdone[half]; reports pass via g_gpassed.
// ---------------------------------------------------------------------------
__device__ __forceinline__ void gather_block(
    const int*   __restrict__ idx,
    const float* __restrict__ w,
    const float* __restrict__ bias,
    float*       __restrict__ out,
    int half, int o0, SmemG& s)
{
    const int tid = threadIdx.x;
    const int wo  = tid >> 5;
    const int l   = tid & 31;

    // Stage idx/w/bias first (overlaps with the wait below)
    if (tid < 64) {
        s.sidx4[tid >> 3][tid & 7] =
            ((const int4*)idx)[(size_t)(o0 + (tid >> 3)) * 8 + (tid & 7)];
    } else if (tid < 128) {
        const int u = tid - 64;
        s.sw4[u >> 3][u & 7] =
            ((const float4*)w)[(size_t)(o0 + (u >> 3)) * 8 + (u & 7)];
    } else if (tid < 128 + OTILE) {
        s.sbias[tid - 128] = bias[o0 + (tid - 128)];
    }

    // Acquire: wait until this half's transpose fully arrived.
    if (tid == 0) {
        while (*(volatile int*)&g_tdone[half] < TSTRIP_H) __nanosleep(64);
        __threadfence();
        atomicAdd(&g_gpassed, 1);
    }
    __syncthreads();

    const uint4* __restrict__ xt16 =
        reinterpret_cast<const uint4*>(g_xt_h) + (size_t)half * 32 + l;

    float a0 = 0.f, a1 = 0.f, a2 = 0.f, a3 = 0.f;
    float a4 = 0.f, a5 = 0.f, a6 = 0.f, a7 = 0.f;

    #pragma unroll
    for (int k4 = 0; k4 < K_DIM / 4; k4++) {
        const int4   ii = s.sidx4[wo][k4];
        const float4 ww = s.sw4[wo][k4];
        const uint4 v0 = __ldg(&xt16[(size_t)ii.x * 64]);
        const uint4 v1 = __ldg(&xt16[(size_t)ii.y * 64]);
        const uint4 v2 = __ldg(&xt16[(size_t)ii.z * 64]);
        const uint4 v3 = __ldg(&xt16[(size_t)ii.w * 64]);

        {
            const float2 f0 = u32_to_f2(v0.x), f1 = u32_to_f2(v0.y);
            const float2 f2 = u32_to_f2(v0.z), f3 = u32_to_f2(v0.w);
            a0 += f0.x * ww.x; a1 += f0.y * ww.x;
            a2 += f1.x * ww.x; a3 += f1.y * ww.x;
            a4 += f2.x * ww.x; a5 += f2.y * ww.x;
            a6 += f3.x * ww.x; a7 += f3.y * ww.x;
        }
        {
            const float2 f0 = u32_to_f2(v1.x), f1 = u32_to_f2(v1.y);
            const float2 f2 = u32_to_f2(v1.z), f3 = u32_to_f2(v1.w);
            a0 += f0.x * ww.y; a1 += f0.y * ww.y;
            a2 += f1.x * ww.y; a3 += f1.y * ww.y;
            a4 += f2.x * ww.y; a5 += f2.y * ww.y;
            a6 += f3.x * ww.y; a7 += f3.y * ww.y;
        }
        {
            const float2 f0 = u32_to_f2(v2.x), f1 = u32_to_f2(v2.y);
            const float2 f2 = u32_to_f2(v2.z), f3 = u32_to_f2(v2.w);
            a0 += f0.x * ww.z; a1 += f0.y * ww.z;
            a2 += f1.x * ww.z; a3 += f1.y * ww.z;
            a4 += f2.x * ww.z; a5 += f2.y * ww.z;
            a6 += f3.x * ww.z; a7 += f3.y * ww.z;
        }
        {
            const float2 f0 = u32_to_f2(v3.x), f1 = u32_to_f2(v3.y);
            const float2 f2 = u32_to_f2(v3.z), f3 = u32_to_f2(v3.w);
            a0 += f0.x * ww.w; a1 += f0.y * ww.w;
            a2 += f1.x * ww.w; a3 += f1.y * ww.w;
            a4 += f2.x * ww.w; a5 += f2.y * ww.w;
            a6 += f3.x * ww.w; a7 += f3.y * ww.w;
        }
    }

    const float bv = s.sbias[wo];
    float4 s0 = make_float4(a0 + bv, a1 + bv, a2 + bv, a3 + bv);
    float4 s1 = make_float4(a4 + bv, a5 + bv, a6 + bv, a7 + bv);
    *(float4*)&s.sout[wo][8 * l + 0] = s0;
    *(float4*)&s.sout[wo][8 * l + 4] = s1;
    __syncthreads();

    {
        const int b = half * HALF_B + tid;
        float4 r0, r1;
        r0.x = s.sout[0][tid]; r0.y = s.sout[1][tid];
        r0.z = s.sout[2][tid]; r0.w = s.sout[3][tid];
        r1.x = s.sout[4][tid]; r1.y = s.sout[5][tid];
        r1.z = s.sout[6][tid]; r1.w = s.sout[7][tid];
        float4* dst = reinterpret_cast<float4*>(out + (size_t)b * OUT_DIM + o0);
        dst[0] = r0;
        dst[1] = r1;
    }
}

// ---------------------------------------------------------------------------
// Mega kernel:
//   [0,512):        T-strips(h0)        (512 blocks = one full-chip wave)
//   [512,3072):     interleaved 1:4  T-strip(h1) : G(h0)
//   [3072,5120):    G(h1)
//   5120:           cleanup (waits for all G gates passed, zeroes counters)
// Deadlock-free: every T(h) bid precedes every G(h) bid; CTAs are claimed in
// bid order, so gated counters always reach TSTRIP_H.
// ---------------------------------------------------------------------------
__global__ __launch_bounds__(256) void mega_kernel(
    const float* __restrict__ x,
    const int*   __restrict__ idx,
    const float* __restrict__ w,
    const float* __restrict__ bias,
    float*       __restrict__ out)
{
    __shared__ SmemU sm;
    const int bx = blockIdx.x;

    if (bx < TSTRIP_H) {
        transpose_strip(x, bx, 0, sm.t);
    } else if (bx < TSTRIP_H + TSTRIP_H + GBLK_H) {
        const int r   = bx - TSTRIP_H;         // 0..2559
        const int grp = r / 5;                 // 0..511
        const int rem = r - 5 * grp;
        if (rem == 0) {
            transpose_strip(x, grp, 1, sm.t);
        } else {
            gather_block(idx, w, bias, out, 0, (grp * 4 + rem - 1) * OTILE, sm.g);
        }
    } else if (bx < GRID_WORK) {
        const int j = bx - (TSTRIP_H + TSTRIP_H + GBLK_H);
        gather_block(idx, w, bias, out, 1, j * OTILE, sm.g);
    } else {
        // Cleanup: once every gather block has passed its gate, nobody reads
        // the counters again -> safe to zero for the next graph replay.
        if (threadIdx.x == 0) {
            while (*(volatile int*)&g_gpassed < 2 * GBLK_H) __nanosleep(128);
            g_tdone[0] = 0;
            g_tdone[1] = 0;
            g_gpassed  = 0;
        }
    }
}

// ---------------------------------------------------------------------------
// Launch: single self-resetting kernel.
// ---------------------------------------------------------------------------
extern "C" void kernel_launch(void* const* d_in, const int* in_sizes, int n_in,
                              void* d_out, int out_size) {
    const float* x    = (const float*)d_in[0];
    const int*   idx  = (const int*)  d_in[1];
    const float* w    = (const float*)d_in[2];
    const float* bias = (const float*)d_in[3];
    float*       out  = (float*)d_out;

    mega_kernel<<<GRID_TOTAL, 256>>>(x, idx, w, bias, out);
}

// round 13
// speedup vs baseline: 1.0971x; 1.0971x over previous
#include <cuda_runtime.h>
#include <cuda_fp16.h>
#include <cstdint>

// Problem constants
#define B_DIM   512
#define HALF_B  256
#define IN_DIM  65536
#define OUT_DIM 16384
#define K_DIM   32
#define OTILE   8

#define TBLK_H  4096            // transpose tiles per half
#define GBLK_H  2048            // gather blocks per half
#define GRID_TOTAL (2 * TBLK_H + 2 * GBLK_H)   // 12288 (same as R9)

// 64 MB scratch for transposed x in fp16: xt[in][b]
__device__ __half g_xt_h[(size_t)IN_DIM * B_DIM];

// Gating state. Zero at load; the LAST gather block to pass its gate zeroes
// everything for the next graph replay (no reset launch, no cleanup block).
__device__ int g_tdone[2];
__device__ int g_gpassed;

// Bit-reinterpretation helpers
__device__ __forceinline__ unsigned int h2_to_u32(__half2 h) {
    union { __half2 h; unsigned int u; } c; c.h = h; return c.u;
}
__device__ __forceinline__ float2 u32_to_f2(unsigned int u) {
    union { unsigned int u; __half2 h; } c; c.u = u;
    return __half22float2(c.h);
}

// Shared-memory shapes (union -> fused footprint = max, not sum)
struct SmemT {
    float4 tile4[32][33];                      // 16.9 KB
};
struct SmemG {
    int4   sidx4[OTILE][K_DIM / 4];
    float4 sw4[OTILE][K_DIM / 4];
    float  sbias[OTILE];
    float  sout[OTILE][HALF_B + 8];
};
union SmemU { SmemT t; SmemG g; };

// ---------------------------------------------------------------------------
// Transpose tile body: 32 b-rows x 128 in-cols of x -> fp16 xt.
// Arrives on g_tdone[half] when its gmem stores are visible.
// ---------------------------------------------------------------------------
__device__ __forceinline__ void transpose_tile(
    const float* __restrict__ x, int in0, int b0, int half, SmemT& s)
{
    const int t = threadIdx.x;

    const int c4 = t & 31;
    const int r0 = t >> 5;
    #pragma unroll
    for (int it = 0; it < 4; it++) {
        const int r = r0 + 8 * it;
        s.tile4[r][c4] =
            *(const float4*)&x[(size_t)(b0 + r) * IN_DIM + in0 + 4 * c4];
    }
    __syncthreads();

    const int i = t >> 1;                      // in-row 0..127
    const int p = t & 1;                       // b-chunk (16 b = 32B)
    const int c  = i >> 2;
    const int cc = i & 3;

    __half2 h2[8];
    #pragma unroll
    for (int j = 0; j < 8; j++) {
        const float f0 = ((const float*)&s.tile4[16 * p + 2 * j + 0][c])[cc];
        const float f1 = ((const float*)&s.tile4[16 * p + 2 * j + 1][c])[cc];
        h2[j] = __floats2half2_rn(f0, f1);
    }
    uint4 u0, u1;
    u0.x = h2_to_u32(h2[0]); u0.y = h2_to_u32(h2[1]);
    u0.z = h2_to_u32(h2[2]); u0.w = h2_to_u32(h2[3]);
    u1.x = h2_to_u32(h2[4]); u1.y = h2_to_u32(h2[5]);
    u1.z = h2_to_u32(h2[6]); u1.w = h2_to_u32(h2[7]);

    uint4* dst = (uint4*)&g_xt_h[(size_t)(in0 + i) * B_DIM + b0 + 16 * p];
    dst[0] = u0;
    dst[1] = u1;

    __syncthreads();
    if (t == 0) {
        __threadfence();                       // release stores
        atomicAdd(&g_tdone[half], 1);
    }
}

// ---------------------------------------------------------------------------
// Gather block body: 8 outputs x one b-half. Warp per output; lane owns
// 8 b-rows via one LDG.128 per (o,k) -> 512B contiguous column reads.
// Gates on g_tdone[half]; the LAST block to pass any gate resets all state.
// ---------------------------------------------------------------------------
__device__ __forceinline__ void gather_block(
    const int*   __restrict__ idx,
    const float* __restrict__ w,
    const float* __restrict__ bias,
    float*       __restrict__ out,
    int half, int o0, SmemG& s)
{
    const int tid = threadIdx.x;
    const int wo  = tid >> 5;
    const int l   = tid & 31;

    // Stage idx/w/bias first (overlaps with the wait below)
    if (tid < 64) {
        s.sidx4[tid >> 3][tid & 7] =
            ((const int4*)idx)[(size_t)(o0 + (tid >> 3)) * 8 + (tid & 7)];
    } else if (tid < 128) {
        const int u = tid - 64;
        s.sw4[u >> 3][u & 7] =
            ((const float4*)w)[(size_t)(o0 + (u >> 3)) * 8 + (u & 7)];
    } else if (tid < 128 + OTILE) {
        s.sbias[tid - 128] = bias[o0 + (tid - 128)];
    }

    // Acquire: wait until this half's transpose fully arrived.
    if (tid == 0) {
        while (*(volatile int*)&g_tdone[half] < TBLK_H) __nanosleep(64);
        __threadfence();
        const int old = atomicAdd(&g_gpassed, 1);
        if (old == 2 * GBLK_H - 1) {
            // Every gather block chip-wide has passed its gate: no block will
            // read these again this call. Zero for the next graph replay.
            g_tdone[0] = 0;
            g_tdone[1] = 0;
            g_gpassed  = 0;
        }
    }
    __syncthreads();

    const uint4* __restrict__ xt16 =
        reinterpret_cast<const uint4*>(g_xt_h) + (size_t)half * 32 + l;

    float a0 = 0.f, a1 = 0.f, a2 = 0.f, a3 = 0.f;
    float a4 = 0.f, a5 = 0.f, a6 = 0.f, a7 = 0.f;

    #pragma unroll
    for (int k4 = 0; k4 < K_DIM / 4; k4++) {
        const int4   ii = s.sidx4[wo][k4];
        const float4 ww = s.sw4[wo][k4];
        const uint4 v0 = __ldg(&xt16[(size_t)ii.x * 64]);
        const uint4 v1 = __ldg(&xt16[(size_t)ii.y * 64]);
        const uint4 v2 = __ldg(&xt16[(size_t)ii.z * 64]);
        const uint4 v3 = __ldg(&xt16[(size_t)ii.w * 64]);

        {
            const float2 f0 = u32_to_f2(v0.x), f1 = u32_to_f2(v0.y);
            const float2 f2 = u32_to_f2(v0.z), f3 = u32_to_f2(v0.w);
            a0 += f0.x * ww.x; a1 += f0.y * ww.x;
            a2 += f1.x * ww.x; a3 += f1.y * ww.x;
            a4 += f2.x * ww.x; a5 += f2.y * ww.x;
            a6 += f3.x * ww.x; a7 += f3.y * ww.x;
        }
        {
            const float2 f0 = u32_to_f2(v1.x), f1 = u32_to_f2(v1.y);
            const float2 f2 = u32_to_f2(v1.z), f3 = u32_to_f2(v1.w);
            a0 += f0.x * ww.y; a1 += f0.y * ww.y;
            a2 += f1.x * ww.y; a3 += f1.y * ww.y;
            a4 += f2.x * ww.y; a5 += f2.y * ww.y;
            a6 += f3.x * ww.y; a7 += f3.y * ww.y;
        }
        {
            const float2 f0 = u32_to_f2(v2.x), f1 = u32_to_f2(v2.y);
            const float2 f2 = u32_to_f2(v2.z), f3 = u32_to_f2(v2.w);
            a0 += f0.x * ww.z; a1 += f0.y * ww.z;
            a2 += f1.x * ww.z; a3 += f1.y * ww.z;
            a4 += f2.x * ww.z; a5 += f2.y * ww.z;
            a6 += f3.x * ww.z; a7 += f3.y * ww.z;
        }
        {
            const float2 f0 = u32_to_f2(v3.x), f1 = u32_to_f2(v3.y);
            const float2 f2 = u32_to_f2(v3.z), f3 = u32_to_f2(v3.w);
            a0 += f0.x * ww.w; a1 += f0.y * ww.w;
            a2 += f1.x * ww.w; a3 += f1.y * ww.w;
            a4 += f2.x * ww.w; a5 += f2.y * ww.w;
            a6 += f3.x * ww.w; a7 += f3.y * ww.w;
        }
    }

    const float bv = s.sbias[wo];
    float4 s0 = make_float4(a0 + bv, a1 + bv, a2 + bv, a3 + bv);
    float4 s1 = make_float4(a4 + bv, a5 + bv, a6 + bv, a7 + bv);
    *(float4*)&s.sout[wo][8 * l + 0] = s0;
    *(float4*)&s.sout[wo][8 * l + 4] = s1;
    __syncthreads();

    {
        const int b = half * HALF_B + tid;
        float4 r0, r1;
        r0.x = s.sout[0][tid]; r0.y = s.sout[1][tid];
        r0.z = s.sout[2][tid]; r0.w = s.sout[3][tid];
        r1.x = s.sout[4][tid]; r1.y = s.sout[5][tid];
        r1.z = s.sout[6][tid]; r1.w = s.sout[7][tid];
        float4* dst = reinterpret_cast<float4*>(out + (size_t)b * OUT_DIM + o0);
        dst[0] = r0;
        dst[1] = r1;
    }
}

// ---------------------------------------------------------------------------
// Mega kernel (R9 structure, grid exactly 12288):
//   [0,4096):        T(h0)
//   [4096,10240):    interleaved 2:1  T(h1) : G(h0)
//   [10240,12288):   G(h1)
// Deadlock-free: every T(h) bid precedes every G(h) bid; CTAs are claimed in
// bid order, so gated counters always reach TBLK_H.
// ---------------------------------------------------------------------------
__global__ __launch_bounds__(256) void mega_kernel(
    const float* __restrict__ x,
    const int*   __restrict__ idx,
    const float* __restrict__ w,
    const float* __restrict__ bias,
    float*       __restrict__ out)
{
    __shared__ SmemU sm;
    const int bx = blockIdx.x;

    if (bx < TBLK_H) {
        // T(h0)
        const int j = bx;
        transpose_tile(x, (j & 511) << 7, (j >> 9) * 32, 0, sm.t);
    } else if (bx < TBLK_H + TBLK_H + GBLK_H) {
        const int r   = bx - TBLK_H;           // 0..6143
        const int grp = r / 3;                 // 0..2047
        const int rem = r - 3 * grp;
        if (rem < 2) {
            // T(h1)
            const int j = 2 * grp + rem;       // 0..4095
            transpose_tile(x, (j & 511) << 7, HALF_B + (j >> 9) * 32, 1, sm.t);
        } else {
            // G(h0)
            gather_block(idx, w, bias, out, 0, grp * OTILE, sm.g);
        }
    } else {
        // G(h1)
        const int j = bx - (TBLK_H + TBLK_H + GBLK_H);
        gather_block(idx, w, bias, out, 1, j * OTILE, sm.g);
    }
}

// ---------------------------------------------------------------------------
// Launch: single kernel, self-resetting via last-gate-passer.
// ---------------------------------------------------------------------------
extern "C" void kernel_launch(void* const* d_in, const int* in_sizes, int n_in,
                              void* d_out, int out_size) {
    const float* x    = (const float*)d_in[0];
    const int*   idx  = (const int*)  d_in[1];
    const float* w    = (const float*)d_in[2];
    const float* bias = (const float*)d_in[3];
    float*       out  = (float*)d_out;

    mega_kernel<<<GRID_TOTAL, 256>>>(x, idx, w, bias, out);
}

// round 14
// speedup vs baseline: 1.1177x; 1.0188x over previous
#include <cuda_runtime.h>
#include <cuda_fp16.h>
#include <cstdint>

// Problem constants
#define B_DIM   512
#define HALF_B  256
#define IN_DIM  65536
#define OUT_DIM 16384
#define K_DIM   32
#define OTILE   8

#define TBLK_H  4096            // transpose tiles per half (1024 in-tiles x 4 bands)
#define GBLK_H  2048            // gather blocks per half
#define GRID_TOTAL (2 * TBLK_H + 2 * GBLK_H)   // 12288

// 64 MB scratch for transposed x in fp16: xt[in][b]
__device__ __half g_xt_h[(size_t)IN_DIM * B_DIM];

// Gating state. Zero at load; the LAST gather block to pass its gate zeroes
// everything for the next graph replay.
__device__ int g_tdone[2];
__device__ int g_gpassed;

// Bit-reinterpretation helpers
__device__ __forceinline__ unsigned int h2_to_u32(__half2 h) {
    union { __half2 h; unsigned int u; } c; c.h = h; return c.u;
}
__device__ __forceinline__ float2 u32_to_f2(unsigned int u) {
    union { unsigned int u; __half2 h; } c; c.u = u;
    return __half22float2(c.h);
}

// Shared-memory shapes (union -> fused footprint = max, not sum)
struct SmemT {
    float4 tile4[64][17];                      // 64b x 64in tile, padded (17.4KB)
};
struct SmemG {
    int4   sidx4[OTILE][K_DIM / 4];
    float4 sw4[OTILE][K_DIM / 4];
    float  sbias[OTILE];
    float  sout[OTILE][HALF_B + 8];
};
union SmemU { SmemT t; SmemG g; };

// ---------------------------------------------------------------------------
// Transpose tile body: 64 b-rows x 64 in-cols of x -> fp16 xt.
// KEY: per xt in-row this tile covers 64 b's = 128 BYTES -> every xt store
// line is fully written and 128B-aligned (b0 multiple of 64). No partial-line
// DRAM write amplification, half the store wavefronts of the 32x128 tile.
// ---------------------------------------------------------------------------
__device__ __forceinline__ void transpose_tile(
    const float* __restrict__ x, int in0, int b0, int half, SmemT& s)
{
    const int t = threadIdx.x;

    // Load: 16 lanes x 16B = 256B contiguous per b-row segment; 2 rows/warp.
    const int c4 = t & 15;                     // float4 col 0..15
    const int r0 = t >> 4;                     // 0..15
    #pragma unroll
    for (int it = 0; it < 4; it++) {
        const int r = r0 + 16 * it;            // b-row 0..63
        s.tile4[r][c4] =
            *(const float4*)&x[(size_t)(b0 + r) * IN_DIM + in0 + 4 * c4];
    }
    __syncthreads();

    // Convert + store: thread owns in-row i = t>>2, 16-b chunk p = t&3 (32B).
    // 4 lanes (p=0..3) of a quad cover one full 128B xt line.
    const int i  = t >> 2;                     // in-row 0..63
    const int p  = t & 3;
    const int c  = i >> 2;
    const int cc = i & 3;

    __half2 h2[8];
    #pragma unroll
    for (int j = 0; j < 8; j++) {
        const float f0 = ((const float*)&s.tile4[16 * p + 2 * j + 0][c])[cc];
        const float f1 = ((const float*)&s.tile4[16 * p + 2 * j + 1][c])[cc];
        h2[j] = __floats2half2_rn(f0, f1);
    }
    uint4 u0, u1;
    u0.x = h2_to_u32(h2[0]); u0.y = h2_to_u32(h2[1]);
    u0.z = h2_to_u32(h2[2]); u0.w = h2_to_u32(h2[3]);
    u1.x = h2_to_u32(h2[4]); u1.y = h2_to_u32(h2[5]);
    u1.z = h2_to_u32(h2[6]); u1.w = h2_to_u32(h2[7]);

    uint4* dst = (uint4*)&g_xt_h[(size_t)(in0 + i) * B_DIM + b0 + 16 * p];
    dst[0] = u0;
    dst[1] = u1;

    __syncthreads();
    if (t == 0) {
        __threadfence();                       // release stores
        atomicAdd(&g_tdone[half], 1);
    }
}

// ---------------------------------------------------------------------------
// Gather block body: 8 outputs x one b-half. Warp per output; lane owns
// 8 b-rows via one LDG.128 per (o,k) -> 512B contiguous column reads.
// Gates on g_tdone[half]; the LAST block to pass any gate resets all state.
// ---------------------------------------------------------------------------
__device__ __forceinline__ void gather_block(
    const int*   __restrict__ idx,
    const float* __restrict__ w,
    const float* __restrict__ bias,
    float*       __restrict__ out,
    int half, int o0, SmemG& s)
{
    const int tid = threadIdx.x;
    const int wo  = tid >> 5;
    const int l   = tid & 31;

    // Stage idx/w/bias first (overlaps with the wait below)
    if (tid < 64) {
        s.sidx4[tid >> 3][tid & 7] =
            ((const int4*)idx)[(size_t)(o0 + (tid >> 3)) * 8 + (tid & 7)];
    } else if (tid < 128) {
        const int u = tid - 64;
        s.sw4[u >> 3][u & 7] =
            ((const float4*)w)[(size_t)(o0 + (u >> 3)) * 8 + (u & 7)];
    } else if (tid < 128 + OTILE) {
        s.sbias[tid - 128] = bias[o0 + (tid - 128)];
    }

    // Acquire: wait until this half's transpose fully arrived.
    if (tid == 0) {
        while (*(volatile int*)&g_tdone[half] < TBLK_H) __nanosleep(64);
        __threadfence();
        const int old = atomicAdd(&g_gpassed, 1);
        if (old == 2 * GBLK_H - 1) {
            // Every gather block chip-wide has passed its gate: nobody reads
            // these again this call. Zero for the next graph replay.
            g_tdone[0] = 0;
            g_tdone[1] = 0;
            g_gpassed  = 0;
        }
    }
    __syncthreads();

    const uint4* __restrict__ xt16 =
        reinterpret_cast<const uint4*>(g_xt_h) + (size_t)half * 32 + l;

    float a0 = 0.f, a1 = 0.f, a2 = 0.f, a3 = 0.f;
    float a4 = 0.f, a5 = 0.f, a6 = 0.f, a7 = 0.f;

    #pragma unroll
    for (int k4 = 0; k4 < K_DIM / 4; k4++) {
        const int4   ii = s.sidx4[wo][k4];
        const float4 ww = s.sw4[wo][k4];
        const uint4 v0 = __ldg(&xt16[(size_t)ii.x * 64]);
        const uint4 v1 = __ldg(&xt16[(size_t)ii.y * 64]);
        const uint4 v2 = __ldg(&xt16[(size_t)ii.z * 64]);
        const uint4 v3 = __ldg(&xt16[(size_t)ii.w * 64]);

        {
            const float2 f0 = u32_to_f2(v0.x), f1 = u32_to_f2(v0.y);
            const float2 f2 = u32_to_f2(v0.z), f3 = u32_to_f2(v0.w);
            a0 += f0.x * ww.x; a1 += f0.y * ww.x;
            a2 += f1.x * ww.x; a3 += f1.y * ww.x;
            a4 += f2.x * ww.x; a5 += f2.y * ww.x;
            a6 += f3.x * ww.x; a7 += f3.y * ww.x;
        }
        {
            const float2 f0 = u32_to_f2(v1.x), f1 = u32_to_f2(v1.y);
            const float2 f2 = u32_to_f2(v1.z), f3 = u32_to_f2(v1.w);
            a0 += f0.x * ww.y; a1 += f0.y * ww.y;
            a2 += f1.x * ww.y; a3 += f1.y * ww.y;
            a4 += f2.x * ww.y; a5 += f2.y * ww.y;
            a6 += f3.x * ww.y; a7 += f3.y * ww.y;
        }
        {
            const float2 f0 = u32_to_f2(v2.x), f1 = u32_to_f2(v2.y);
            const float2 f2 = u32_to_f2(v2.z), f3 = u32_to_f2(v2.w);
            a0 += f0.x * ww.z; a1 += f0.y * ww.z;
            a2 += f1.x * ww.z; a3 += f1.y * ww.z;
            a4 += f2.x * ww.z; a5 += f2.y * ww.z;
            a6 += f3.x * ww.z; a7 += f3.y * ww.z;
        }
        {
            const float2 f0 = u32_to_f2(v3.x), f1 = u32_to_f2(v3.y);
            const float2 f2 = u32_to_f2(v3.z), f3 = u32_to_f2(v3.w);
            a0 += f0.x * ww.w; a1 += f0.y * ww.w;
            a2 += f1.x * ww.w; a3 += f1.y * ww.w;
            a4 += f2.x * ww.w; a5 += f2.y * ww.w;
            a6 += f3.x * ww.w; a7 += f3.y * ww.w;
        }
    }

    const float bv = s.sbias[wo];
    float4 s0 = make_float4(a0 + bv, a1 + bv, a2 + bv, a3 + bv);
    float4 s1 = make_float4(a4 + bv, a5 + bv, a6 + bv, a7 + bv);
    *(float4*)&s.sout[wo][8 * l + 0] = s0;
    *(float4*)&s.sout[wo][8 * l + 4] = s1;
    __syncthreads();

    {
        const int b = half * HALF_B + tid;
        float4 r0, r1;
        r0.x = s.sout[0][tid]; r0.y = s.sout[1][tid];
        r0.z = s.sout[2][tid]; r0.w = s.sout[3][tid];
        r1.x = s.sout[4][tid]; r1.y = s.sout[5][tid];
        r1.z = s.sout[6][tid]; r1.w = s.sout[7][tid];
        float4* dst = reinterpret_cast<float4*>(out + (size_t)b * OUT_DIM + o0);
        dst[0] = r0;
        dst[1] = r1;
    }
}

// ---------------------------------------------------------------------------
// Mega kernel (R13 schedule, grid exactly 12288):
//   [0,4096):        T(h0)
//   [4096,10240):    interleaved 2:1  T(h1) : G(h0)
//   [10240,12288):   G(h1)
// T tile decode: j in [0,4096) -> in0 = (j & 1023)*64, band = j >> 10 (0..3),
// b0 = half*256 + band*64.
// Deadlock-free: every T(h) bid precedes every G(h) bid; CTAs are claimed in
// bid order, so gated counters always reach TBLK_H.
// ---------------------------------------------------------------------------
__global__ __launch_bounds__(256) void mega_kernel(
    const float* __restrict__ x,
    const int*   __restrict__ idx,
    const float* __restrict__ w,
    const float* __restrict__ bias,
    float*       __restrict__ out)
{
    __shared__ SmemU sm;
    const int bx = blockIdx.x;

    if (bx < TBLK_H) {
        // T(h0)
        const int j = bx;
        transpose_tile(x, (j & 1023) << 6, (j >> 10) << 6, 0, sm.t);
    } else if (bx < TBLK_H + TBLK_H + GBLK_H) {
        const int r   = bx - TBLK_H;           // 0..6143
        const int grp = r / 3;                 // 0..2047
        const int rem = r - 3 * grp;
        if (rem < 2) {
            // T(h1)
            const int j = 2 * grp + rem;       // 0..4095
            transpose_tile(x, (j & 1023) << 6, HALF_B + ((j >> 10) << 6), 1, sm.t);
        } else {
            // G(h0)
            gather_block(idx, w, bias, out, 0, grp * OTILE, sm.g);
        }
    } else {
        // G(h1)
        const int j = bx - (TBLK_H + TBLK_H + GBLK_H);
        gather_block(idx, w, bias, out, 1, j * OTILE, sm.g);
    }
}

// ---------------------------------------------------------------------------
// Launch: single kernel, self-resetting via last-gate-passer.
// ---------------------------------------------------------------------------
extern "C" void kernel_launch(void* const* d_in, const int* in_sizes, int n_in,
                              void* d_out, int out_size) {
    const float* x    = (const float*)d_in[0];
    const int*   idx  = (const int*)  d_in[1];
    const float* w    = (const float*)d_in[2];
    const float* bias = (const float*)d_in[3];
    float*       out  = (float*)d_out;

    mega_kernel<<<GRID_TOTAL, 256>>>(x, idx, w, bias, out);
}

// round 15
// speedup vs baseline: 1.1234x; 1.0051x over previous
#include <cuda_runtime.h>
#include <cuda_fp16.h>
#include <cstdint>

// Problem constants
#define B_DIM   512
#define QB      128             // batch rows per quarter
#define IN_DIM  65536
#define OUT_DIM 16384
#define K_DIM   32
#define OTILE   16              // outputs per gather block

#define TBLK_Q  2048            // transpose tiles per quarter (1024 in x 2 bands)
#define GBLK_Q  1024            // gather blocks per quarter (16384/16)
#define GRID_TOTAL (4 * TBLK_Q + 4 * GBLK_Q)   // 12288

// 64 MB scratch for transposed x in fp16: xt[in][b]
__device__ __half g_xt_h[(size_t)IN_DIM * B_DIM];

// Gating state. Zero at load; the LAST gather block to pass its gate zeroes
// everything for the next graph replay.
__device__ int g_tdone[4];
__device__ int g_gpassed;

// Bit-reinterpretation helpers
__device__ __forceinline__ unsigned int h2_to_u32(__half2 h) {
    union { __half2 h; unsigned int u; } c; c.h = h; return c.u;
}
__device__ __forceinline__ float2 u32_to_f2(unsigned int u) {
    union { unsigned int u; __half2 h; } c; c.u = u;
    return __half22float2(c.h);
}

// Shared-memory shapes (union -> fused footprint = max, not sum)
struct SmemT {
    float4 tile4[64][17];                      // 64b x 64in tile, padded (17.4KB)
};
struct SmemG {
    int4   sidx4[OTILE][K_DIM / 4];
    float4 sw4[OTILE][K_DIM / 4];
    float  sbias[OTILE];
    float  sout[OTILE][QB + 4];                // [o][b-local], stride 132
};
union SmemU { SmemT t; SmemG g; };

// ---------------------------------------------------------------------------
// Transpose tile body: 64 b-rows x 64 in-cols of x -> fp16 xt (R14 body).
// Arrives on g_tdone[q].
// ---------------------------------------------------------------------------
__device__ __forceinline__ void transpose_tile(
    const float* __restrict__ x, int in0, int b0, int q, SmemT& s)
{
    const int t = threadIdx.x;

    const int c4 = t & 15;                     // float4 col 0..15
    const int r0 = t >> 4;                     // 0..15
    #pragma unroll
    for (int it = 0; it < 4; it++) {
        const int r = r0 + 16 * it;            // b-row 0..63
        s.tile4[r][c4] =
            *(const float4*)&x[(size_t)(b0 + r) * IN_DIM + in0 + 4 * c4];
    }
    __syncthreads();

    const int i  = t >> 2;                     // in-row 0..63
    const int p  = t & 3;                      // 16-b chunk (32B)
    const int c  = i >> 2;
    const int cc = i & 3;

    __half2 h2[8];
    #pragma unroll
    for (int j = 0; j < 8; j++) {
        const float f0 = ((const float*)&s.tile4[16 * p + 2 * j + 0][c])[cc];
        const float f1 = ((const float*)&s.tile4[16 * p + 2 * j + 1][c])[cc];
        h2[j] = __floats2half2_rn(f0, f1);
    }
    uint4 u0, u1;
    u0.x = h2_to_u32(h2[0]); u0.y = h2_to_u32(h2[1]);
    u0.z = h2_to_u32(h2[2]); u0.w = h2_to_u32(h2[3]);
    u1.x = h2_to_u32(h2[4]); u1.y = h2_to_u32(h2[5]);
    u1.z = h2_to_u32(h2[6]); u1.w = h2_to_u32(h2[7]);

    uint4* dst = (uint4*)&g_xt_h[(size_t)(in0 + i) * B_DIM + b0 + 16 * p];
    dst[0] = u0;
    dst[1] = u1;

    __syncthreads();
    if (t == 0) {
        __threadfence();                       // release stores
        atomicAdd(&g_tdone[q], 1);
    }
}

// ---------------------------------------------------------------------------
// Gather block body: 16 outputs x one b-quarter. Warp handles TWO outputs:
// lanes 0-15 -> output 2*wo, lanes 16-31 -> 2*wo+1. Each lane owns 8 b-rows
// via one LDG.128 per (o,k) -> 256B contiguous column read per output.
// Gates on g_tdone[q]; the LAST block to pass any gate resets all state.
// ---------------------------------------------------------------------------
__device__ __forceinline__ void gather_block(
    const int*   __restrict__ idx,
    const float* __restrict__ w,
    const float* __restrict__ bias,
    float*       __restrict__ out,
    int q, int o0, SmemG& s)
{
    const int tid = threadIdx.x;
    const int wo  = tid >> 5;                  // warp 0..7
    const int l   = tid & 31;
    const int oo  = 2 * wo + (l >> 4);         // this lane's output 0..15
    const int ls  = l & 15;                    // lane-slot within output

    // Stage idx/w/bias (256 threads cover 128 int4 + 128 float4)
    if (tid < 128) {
        s.sidx4[tid >> 3][tid & 7] =
            ((const int4*)idx)[(size_t)(o0 + (tid >> 3)) * 8 + (tid & 7)];
        if (tid < OTILE) s.sbias[tid] = bias[o0 + tid];
    } else {
        const int u = tid - 128;
        s.sw4[u >> 3][u & 7] =
            ((const float4*)w)[(size_t)(o0 + (u >> 3)) * 8 + (u & 7)];
    }

    // Acquire: wait until this quarter's transpose fully arrived.
    if (tid == 0) {
        while (*(volatile int*)&g_tdone[q] < TBLK_Q) __nanosleep(64);
        __threadfence();
        const int old = atomicAdd(&g_gpassed, 1);
        if (old == 4 * GBLK_Q - 1) {
            // All gather blocks chip-wide have passed: nobody reads these
            // again this call. Zero for the next graph replay.
            g_tdone[0] = 0; g_tdone[1] = 0;
            g_tdone[2] = 0; g_tdone[3] = 0;
            g_gpassed  = 0;
        }
    }
    __syncthreads();

    // xt row = 512 halves = 64 uint4 slots; quarter q = slots [16q, 16q+16).
    const uint4* __restrict__ xt16 =
        reinterpret_cast<const uint4*>(g_xt_h) + (size_t)q * 16 + ls;

    float a0 = 0.f, a1 = 0.f, a2 = 0.f, a3 = 0.f;
    float a4 = 0.f, a5 = 0.f, a6 = 0.f, a7 = 0.f;

    #pragma unroll
    for (int k4 = 0; k4 < K_DIM / 4; k4++) {
        const int4   ii = s.sidx4[oo][k4];
        const float4 ww = s.sw4[oo][k4];
        const uint4 v0 = __ldg(&xt16[(size_t)ii.x * 64]);
        const uint4 v1 = __ldg(&xt16[(size_t)ii.y * 64]);
        const uint4 v2 = __ldg(&xt16[(size_t)ii.z * 64]);
        const uint4 v3 = __ldg(&xt16[(size_t)ii.w * 64]);

        {
            const float2 f0 = u32_to_f2(v0.x), f1 = u32_to_f2(v0.y);
            const float2 f2 = u32_to_f2(v0.z), f3 = u32_to_f2(v0.w);
            a0 += f0.x * ww.x; a1 += f0.y * ww.x;
            a2 += f1.x * ww.x; a3 += f1.y * ww.x;
            a4 += f2.x * ww.x; a5 += f2.y * ww.x;
            a6 += f3.x * ww.x; a7 += f3.y * ww.x;
        }
        {
            const float2 f0 = u32_to_f2(v1.x), f1 = u32_to_f2(v1.y);
            const float2 f2 = u32_to_f2(v1.z), f3 = u32_to_f2(v1.w);
            a0 += f0.x * ww.y; a1 += f0.y * ww.y;
            a2 += f1.x * ww.y; a3 += f1.y * ww.y;
            a4 += f2.x * ww.y; a5 += f2.y * ww.y;
            a6 += f3.x * ww.y; a7 += f3.y * ww.y;
        }
        {
            const float2 f0 = u32_to_f2(v2.x), f1 = u32_to_f2(v2.y);
            const float2 f2 = u32_to_f2(v2.z), f3 = u32_to_f2(v2.w);
            a0 += f0.x * ww.z; a1 += f0.y * ww.z;
            a2 += f1.x * ww.z; a3 += f1.y * ww.z;
            a4 += f2.x * ww.z; a5 += f2.y * ww.z;
            a6 += f3.x * ww.z; a7 += f3.y * ww.z;
        }
        {
            const float2 f0 = u32_to_f2(v3.x), f1 = u32_to_f2(v3.y);
            const float2 f2 = u32_to_f2(v3.z), f3 = u32_to_f2(v3.w);
            a0 += f0.x * ww.w; a1 += f0.y * ww.w;
            a2 += f1.x * ww.w; a3 += f1.y * ww.w;
            a4 += f2.x * ww.w; a5 += f2.y * ww.w;
            a6 += f3.x * ww.w; a7 += f3.y * ww.w;
        }
    }

    const float bv = s.sbias[oo];
    float4 s0 = make_float4(a0 + bv, a1 + bv, a2 + bv, a3 + bv);
    float4 s1 = make_float4(a4 + bv, a5 + bv, a6 + bv, a7 + bv);
    *(float4*)&s.sout[oo][8 * ls + 0] = s0;
    *(float4*)&s.sout[oo][8 * ls + 4] = s1;
    __syncthreads();

    // Coalesced out store: threads 0..127 own b = q*128 + tid, write
    // out[b][o0..o0+15] as four STG.128 (each 32B sector written whole).
    if (tid < QB) {
        const int b = q * QB + tid;
        float4 r0, r1, r2, r3;
        r0.x = s.sout[ 0][tid]; r0.y = s.sout[ 1][tid];
        r0.z = s.sout[ 2][tid]; r0.w = s.sout[ 3][tid];
        r1.x = s.sout[ 4][tid]; r1.y = s.sout[ 5][tid];
        r1.z = s.sout[ 6][tid]; r1.w = s.sout[ 7][tid];
        r2.x = s.sout[ 8][tid]; r2.y = s.sout[ 9][tid];
        r2.z = s.sout[10][tid]; r2.w = s.sout[11][tid];
        r3.x = s.sout[12][tid]; r3.y = s.sout[13][tid];
        r3.z = s.sout[14][tid]; r3.w = s.sout[15][tid];
        float4* dst = reinterpret_cast<float4*>(out + (size_t)b * OUT_DIM + o0);
        dst[0] = r0; dst[1] = r1; dst[2] = r2; dst[3] = r3;
    }
}

// ---------------------------------------------------------------------------
// Mega kernel: quarter pipeline, grid exactly 12288.
//   [0,2048):          T(q0)
//   3 phases of 3072:  2:1  T(q+1) : G(q)   (groups of 3: 2 T, 1 G)
//   [11264,12288):     G(q3)
// T tile decode: j in [0,2048) -> in0 = (j & 1023)*64, band = j >> 10 (0..1),
// b0 = q*128 + band*64.
// Deadlock-free: every T(q) bid precedes every G(q) bid; CTAs are claimed in
// bid order, so gated counters always reach TBLK_Q.
// ---------------------------------------------------------------------------
__global__ __launch_bounds__(256) void mega_kernel(
    const float* __restrict__ x,
    const int*   __restrict__ idx,
    const float* __restrict__ w,
    const float* __restrict__ bias,
    float*       __restrict__ out)
{
    __shared__ SmemU sm;
    const int bx = blockIdx.x;

    if (bx < TBLK_Q) {
        // T(q0)
        const int j = bx;
        transpose_tile(x, (j & 1023) << 6, (j >> 10) << 6, 0, sm.t);
    } else if (bx < TBLK_Q + 3 * (TBLK_Q + GBLK_Q)) {
        const int r     = bx - TBLK_Q;         // 0..9215
        const int phase = r / 3072;            // 0..2
        const int off   = r - phase * 3072;
        const int grp   = off / 3;             // 0..1023
        const int rem   = off - 3 * grp;
        if (rem < 2) {
            // T(q = phase+1)
            const int q = phase + 1;
            const int j = 2 * grp + rem;       // 0..2047
            transpose_tile(x, (j & 1023) << 6,
                           q * QB + ((j >> 10) << 6), q, sm.t);
        } else {
            // G(q = phase)
            gather_block(idx, w, bias, out, phase, grp * OTILE, sm.g);
        }
    } else {
        // G(q3)
        const int j = bx - (TBLK_Q + 3 * (TBLK_Q + GBLK_Q));
        gather_block(idx, w, bias, out, 3, j * OTILE, sm.g);
    }
}

// ---------------------------------------------------------------------------
// Launch: single kernel, self-resetting via last-gate-passer.
// ---------------------------------------------------------------------------
extern "C" void kernel_launch(void* const* d_in, const int* in_sizes, int n_in,
                              void* d_out, int out_size) {
    const float* x    = (const float*)d_in[0];
    const int*   idx  = (const int*)  d_in[1];
    const float* w    = (const float*)d_in[2];
    const float* bias = (const float*)d_in[3];
    float*       out  = (float*)d_out;

    mega_kernel<<<GRID_TOTAL, 256>>>(x, idx, w, bias, out);
}